// round 4
// baseline (speedup 1.0000x reference)
#include <cuda_runtime.h>
#include <cstdint>

#define D 128
#define NMAX 100000

// ---- scratch (static device globals; no allocation allowed) ----
__device__ float  g_h[(size_t)NMAX * D];     // h = x@W + b
__device__ float  g_acc[(size_t)NMAX * D];   // scatter-add accumulator
__device__ float  g_feat[(size_t)NMAX * D];  // BN output / next layer input
__device__ float  g_dinv[NMAX];              // deg^-0.5
__device__ double g_stats[2 * D];            // per-feature sum, sumsq
__device__ float  g_coeff[2 * D];            // BN fused mul, add

// ------------------------------------------------------------------
// Degree: count edges per source node (row), then dinv = rsqrt(cnt+1)
// ------------------------------------------------------------------
__global__ void k_count(const int* __restrict__ ei, int E) {
    for (int i = blockIdx.x * blockDim.x + threadIdx.x; i < E;
         i += gridDim.x * blockDim.x)
        atomicAdd(&g_dinv[ei[i]], 1.0f);
}

__global__ void k_dinv(int M) {
    int i = blockIdx.x * blockDim.x + threadIdx.x;
    if (i < M) g_dinv[i] = rsqrtf(g_dinv[i] + 1.0f);
}

// ------------------------------------------------------------------
// SGEMM: C[M,128] = A[M,128] @ W[128,128] + bias
// 128x128 block tile, BK=16, 256 threads, 8x8 micro-tile per thread
// ------------------------------------------------------------------
__global__ __launch_bounds__(256, 2)
void k_gemm(const float* __restrict__ A, const float* __restrict__ W,
            const float* __restrict__ bias, float* __restrict__ C, int M)
{
    __shared__ float As[16][128];   // [k][row]
    __shared__ float Ws[16][128];   // [k][col]
    const int tid  = threadIdx.x;
    const int m0   = blockIdx.x * 128;
    const int trow = (tid >> 4) << 3;   // 0..120 step 8
    const int tcol = (tid & 15) << 3;   // 0..120 step 8

    float acc[8][8];
    #pragma unroll
    for (int i = 0; i < 8; i++)
        #pragma unroll
        for (int j = 0; j < 8; j++) acc[i][j] = 0.0f;

    for (int k0 = 0; k0 < 128; k0 += 16) {
        // load A tile (128 rows x 16 cols): 512 float4, 2 per thread
        #pragma unroll
        for (int it = 0; it < 2; it++) {
            int q  = tid + it * 256;
            int r  = q >> 2;
            int qc = (q & 3) << 2;         // 0,4,8,12
            int row = m0 + r;
            float4 v = make_float4(0.f, 0.f, 0.f, 0.f);
            if (row < M)
                v = *(const float4*)(A + (size_t)row * 128 + k0 + qc);
            As[qc + 0][r] = v.x; As[qc + 1][r] = v.y;
            As[qc + 2][r] = v.z; As[qc + 3][r] = v.w;
        }
        // load W tile (16 rows x 128 cols)
        #pragma unroll
        for (int it = 0; it < 2; it++) {
            int q = tid + it * 256;
            int k = q >> 5;
            int c = (q & 31) << 2;
            *(float4*)(&Ws[k][c]) =
                *(const float4*)(W + (size_t)(k0 + k) * 128 + c);
        }
        __syncthreads();
        #pragma unroll
        for (int kk = 0; kk < 16; kk++) {
            float a[8], w[8];
            *(float4*)(a)     = *(const float4*)(&As[kk][trow]);
            *(float4*)(a + 4) = *(const float4*)(&As[kk][trow + 4]);
            *(float4*)(w)     = *(const float4*)(&Ws[kk][tcol]);
            *(float4*)(w + 4) = *(const float4*)(&Ws[kk][tcol + 4]);
            #pragma unroll
            for (int i = 0; i < 8; i++)
                #pragma unroll
                for (int j = 0; j < 8; j++)
                    acc[i][j] += a[i] * w[j];
        }
        __syncthreads();
    }

    float bj[8];
    *(float4*)(bj)     = *(const float4*)(bias + tcol);
    *(float4*)(bj + 4) = *(const float4*)(bias + tcol + 4);
    #pragma unroll
    for (int i = 0; i < 8; i++) {
        int row = m0 + trow + i;
        if (row < M) {
            float4 o0 = make_float4(acc[i][0] + bj[0], acc[i][1] + bj[1],
                                    acc[i][2] + bj[2], acc[i][3] + bj[3]);
            float4 o1 = make_float4(acc[i][4] + bj[4], acc[i][5] + bj[5],
                                    acc[i][6] + bj[6], acc[i][7] + bj[7]);
            *(float4*)(C + (size_t)row * 128 + tcol)     = o0;
            *(float4*)(C + (size_t)row * 128 + tcol + 4) = o1;
        }
    }
}

// ------------------------------------------------------------------
// Edge aggregation: one warp per edge (lane owns 4 features),
// 4 edges per iteration for MLP. Vector red.global.add.v4.f32.
// acc[col] += relu(h[row] + ea@We + be) * dinv[row]*dinv[col]
// ------------------------------------------------------------------
__global__ __launch_bounds__(256)
void k_edge(const float* __restrict__ h, const int* __restrict__ ei,
            const float* __restrict__ ea, const float* __restrict__ We,
            const float* __restrict__ be, int E)
{
    const int lane = threadIdx.x & 31;
    const int warp = (blockIdx.x * blockDim.x + threadIdx.x) >> 5;
    const int nw   = (gridDim.x * blockDim.x) >> 5;
    const int f    = lane << 2;

    const float4 w0 = *(const float4*)(We + f);
    const float4 w1 = *(const float4*)(We + D + f);
    const float4 w2 = *(const float4*)(We + 2 * D + f);
    const float4 b4 = *(const float4*)(be + f);

    for (int e0 = warp * 4; e0 < E; e0 += nw * 4) {
        bool   val[4];
        int    cc[4];
        float  a0[4], a1[4], a2[4], nrm[4];
        float4 hv[4];
        #pragma unroll
        for (int u = 0; u < 4; u++) {
            int e  = e0 + u;
            val[u] = (e < E);
            int es = val[u] ? e : e0;
            int r  = ei[es];
            cc[u]  = ei[E + es];
            a0[u]  = ea[3 * es + 0];
            a1[u]  = ea[3 * es + 1];
            a2[u]  = ea[3 * es + 2];
            nrm[u] = g_dinv[r] * g_dinv[cc[u]];
            hv[u]  = *(const float4*)(h + (size_t)r * D + f);
        }
        #pragma unroll
        for (int u = 0; u < 4; u++) {
            float4 v;
            v.x = fmaxf(hv[u].x + b4.x + a0[u]*w0.x + a1[u]*w1.x + a2[u]*w2.x, 0.f) * nrm[u];
            v.y = fmaxf(hv[u].y + b4.y + a0[u]*w0.y + a1[u]*w1.y + a2[u]*w2.y, 0.f) * nrm[u];
            v.z = fmaxf(hv[u].z + b4.z + a0[u]*w0.z + a1[u]*w1.z + a2[u]*w2.z, 0.f) * nrm[u];
            v.w = fmaxf(hv[u].w + b4.w + a0[u]*w0.w + a1[u]*w1.w + a2[u]*w2.w, 0.f) * nrm[u];
            if (val[u]) {
                float* p = g_acc + (size_t)cc[u] * D + f;
                asm volatile("red.global.add.v4.f32 [%0], {%1,%2,%3,%4};"
                             :: "l"(p), "f"(v.x), "f"(v.y), "f"(v.z), "f"(v.w)
                             : "memory");
            }
        }
    }
}

// ------------------------------------------------------------------
// BN stats over relu(acc): per-feature sum & sumsq (double accum)
// ------------------------------------------------------------------
__global__ void k_bnstats(int M) {
    const int f = threadIdx.x;   // 128 threads = 128 features
    double s = 0.0, s2 = 0.0;
    for (int r = blockIdx.x; r < M; r += gridDim.x) {
        float v = fmaxf(g_acc[(size_t)r * D + f], 0.0f);
        s  += (double)v;
        s2 += (double)v * (double)v;
    }
    atomicAdd(&g_stats[f], s);
    atomicAdd(&g_stats[D + f], s2);
}

__global__ void k_bncoeff(const float* __restrict__ g,
                          const float* __restrict__ bt, int M) {
    const int f = threadIdx.x;
    double mean = g_stats[f] / (double)M;
    double var  = g_stats[D + f] / (double)M - mean * mean;
    float mul = g[f] * rsqrtf((float)var + 1e-5f);
    g_coeff[f]     = mul;
    g_coeff[D + f] = bt[f] - (float)mean * mul;
}

// feat = relu(acc) * mul + add   (fused relu + batchnorm affine)
__global__ void k_bnapply(int M) {
    const int nq = M * (D / 4);
    const float4* av = (const float4*)g_acc;
    float4*       ov = (float4*)g_feat;
    const float4* cf = (const float4*)g_coeff;
    for (int i = blockIdx.x * blockDim.x + threadIdx.x; i < nq;
         i += gridDim.x * blockDim.x) {
        int fq = i & 31;
        float4 v   = av[i];
        float4 mul = cf[fq];
        float4 ad  = cf[32 + fq];
        float4 o;
        o.x = fmaxf(v.x, 0.f) * mul.x + ad.x;
        o.y = fmaxf(v.y, 0.f) * mul.y + ad.y;
        o.z = fmaxf(v.z, 0.f) * mul.z + ad.z;
        o.w = fmaxf(v.w, 0.f) * mul.w + ad.w;
        ov[i] = o;
    }
}

// ------------------------------------------------------------------
extern "C" void kernel_launch(void* const* d_in, const int* in_sizes, int n_in,
                              void* d_out, int out_size)
{
    const float* x  = (const float*)d_in[0];
    const int*   ei = (const int*)d_in[1];
    const float* ea = (const float*)d_in[2];
    // per-layer params: W,b,We,be,g,bt at [3..8],[9..14],[15..20]
    const float* Wp[3]  = {(const float*)d_in[3],  (const float*)d_in[9],  (const float*)d_in[15]};
    const float* bp[3]  = {(const float*)d_in[4],  (const float*)d_in[10], (const float*)d_in[16]};
    const float* Wep[3] = {(const float*)d_in[5],  (const float*)d_in[11], (const float*)d_in[17]};
    const float* bep[3] = {(const float*)d_in[6],  (const float*)d_in[12], (const float*)d_in[18]};
    const float* gp[3]  = {(const float*)d_in[7],  (const float*)d_in[13], (const float*)d_in[19]};
    const float* btp[3] = {(const float*)d_in[8],  (const float*)d_in[14], (const float*)d_in[20]};
    const float* Wl = (const float*)d_in[21];
    const float* bl = (const float*)d_in[22];

    const int M = in_sizes[0] / D;   // nodes
    const int E = in_sizes[1] / 2;   // edges

    // IMPORTANT: always resolve __device__ symbols via the runtime.
    // On GB300, the raw host-shadow symbol is ATS-dereferenceable from the
    // GPU (reads host .bss zeros) — a silent wrong-answer, not a trap.
    void *p_h, *p_acc, *p_feat, *p_dinv, *p_stats;
    cudaGetSymbolAddress(&p_h, g_h);
    cudaGetSymbolAddress(&p_acc, g_acc);
    cudaGetSymbolAddress(&p_feat, g_feat);
    cudaGetSymbolAddress(&p_dinv, g_dinv);
    cudaGetSymbolAddress(&p_stats, g_stats);

    // degrees (same for all layers)
    cudaMemsetAsync(p_dinv, 0, (size_t)M * sizeof(float));
    k_count<<<2048, 256>>>(ei, E);
    k_dinv<<<(M + 255) / 256, 256>>>(M);

    const int gemm_grid = (M + 127) / 128;
    const float* in = x;
    for (int L = 0; L < 3; L++) {
        k_gemm<<<gemm_grid, 256>>>(in, Wp[L], bp[L], (float*)p_h, M);
        cudaMemsetAsync(p_acc, 0, (size_t)M * D * sizeof(float));
        k_edge<<<1536, 256>>>((const float*)p_h, ei, ea, Wep[L], bep[L], E);
        cudaMemsetAsync(p_stats, 0, 2 * D * sizeof(double));
        k_bnstats<<<1024, 128>>>(M);
        k_bncoeff<<<1, 128>>>(gp[L], btp[L], M);
        k_bnapply<<<2048, 256>>>(M);
        in = (const float*)p_feat;
    }
    k_gemm<<<gemm_grid, 256>>>((const float*)p_feat, Wl, bl, (float*)d_out, M);
}